// round 2
// baseline (speedup 1.0000x reference)
#include <cuda_runtime.h>
#include <cstdint>

#define N 256
#define NP (N * N)
static const size_t NV = (size_t)N * N * N;

#define TX 32
#define TY 16
#define HX (TX + 4)   // 36
#define HY (TY + 4)   // 20
#define NTHR 512

// ---------------------------------------------------------------------------
// Fully fused NCC-forces kernel: sliding 5-plane z-window.
// Per z-step: stage img/ref halo tile -> horizontal 5-tap sums of the 5
// moment quantities -> vertical 5-tap (per thread) -> push into per-thread
// register ring -> z-box = sum of ring -> epilogue (gradients + force).
// ---------------------------------------------------------------------------
__global__ __launch_bounds__(NTHR, 1) void ncc_fused_kernel(
    const float* __restrict__ img, const float* __restrict__ ref,
    float* __restrict__ out)
{
    __shared__ float st_i[5][HY][HX];
    __shared__ float st_r[5][HY][HX];
    __shared__ float hsum[5][HY][TX];

    const int tx  = threadIdx.x;
    const int ty  = threadIdx.y;
    const int tid = ty * 32 + tx;
    const int gx0 = blockIdx.x * TX;
    const int gy0 = blockIdx.y * TY;
    const int gx  = gx0 + tx;
    const int gy  = gy0 + ty;

    const float npix = 125.0f;
    const float inv_npix = 1.0f / 125.0f;

    // Per-thread register delay lines (planes zp-4 .. zp)
    float hist0[5], hist1[5], hist2[5], hist3[5], hist4[5];
    float ch_i[5], ch_r[5];
#pragma unroll
    for (int k = 0; k < 5; k++) {
        hist0[k] = hist1[k] = hist2[k] = hist3[k] = hist4[k] = 0.0f;
        ch_i[k] = ch_r[k] = 0.0f;
    }

    for (int zp = 0; zp < N + 2; ++zp) {
        const int slot = zp % 5;

        // -------- stage plane zp (zero-padded halo) --------
        if (zp < N) {
            const size_t zoff = (size_t)zp * NP;
#pragma unroll
            for (int base = 0; base < HX * HY; base += NTHR) {
                int p = base + tid;
                if (p < HX * HY) {
                    int ly = p / HX, lx = p - ly * HX;
                    int ggx = gx0 - 2 + lx;
                    int ggy = gy0 - 2 + ly;
                    bool in = (ggx >= 0) & (ggx < N) & (ggy >= 0) & (ggy < N);
                    size_t o = zoff + (size_t)ggy * N + ggx;
                    st_i[slot][ly][lx] = in ? __ldg(img + o) : 0.0f;
                    st_r[slot][ly][lx] = in ? __ldg(ref + o) : 0.0f;
                }
            }
        }
        __syncthreads();

        // -------- horizontal 5-tap sums of the 5 quantities --------
        if (zp < N) {
#pragma unroll
            for (int base = 0; base < HY * TX; base += NTHR) {
                int p = base + tid;
                if (p < HY * TX) {
                    int ly = p >> 5, lx = p & 31;
                    float a0 = 0.f, a1 = 0.f, a2 = 0.f, a3 = 0.f, a4 = 0.f;
#pragma unroll
                    for (int d = 0; d < 5; d++) {
                        float vi = st_i[slot][ly][lx + d];
                        float vr = st_r[slot][ly][lx + d];
                        a0 += vi;
                        a1 += vr;
                        a2 += vi * vi;
                        a3 += vr * vr;
                        a4 += vi * vr;
                    }
                    hsum[0][ly][lx] = a0;
                    hsum[1][ly][lx] = a1;
                    hsum[2][ly][lx] = a2;
                    hsum[3][ly][lx] = a3;
                    hsum[4][ly][lx] = a4;
                }
            }
        }
        __syncthreads();

        // -------- vertical 5-tap + center sample for this thread --------
        float nw0 = 0.f, nw1 = 0.f, nw2 = 0.f, nw3 = 0.f, nw4 = 0.f;
        float cn_i = 0.f, cn_r = 0.f;
        if (zp < N) {
#pragma unroll
            for (int d = 0; d < 5; d++) {
                nw0 += hsum[0][ty + d][tx];
                nw1 += hsum[1][ty + d][tx];
                nw2 += hsum[2][ty + d][tx];
                nw3 += hsum[3][ty + d][tx];
                nw4 += hsum[4][ty + d][tx];
            }
            cn_i = st_i[slot][ty + 2][tx + 2];
            cn_r = st_r[slot][ty + 2][tx + 2];
        }

        // -------- shift register rings, push new --------
#pragma unroll
        for (int k = 0; k < 4; k++) {
            hist0[k] = hist0[k + 1];
            hist1[k] = hist1[k + 1];
            hist2[k] = hist2[k + 1];
            hist3[k] = hist3[k + 1];
            hist4[k] = hist4[k + 1];
            ch_i[k] = ch_i[k + 1];
            ch_r[k] = ch_r[k + 1];
        }
        hist0[4] = nw0; hist1[4] = nw1; hist2[4] = nw2;
        hist3[4] = nw3; hist4[4] = nw4;
        ch_i[4] = cn_i; ch_r[4] = cn_r;

        // -------- epilogue for z = zp - 2 --------
        if (zp >= 2) {
            const int z = zp - 2;
            const int sz = (zp + 3) % 5;   // ring slot holding plane z

            const float sum_i  = hist0[0] + hist0[1] + hist0[2] + hist0[3] + hist0[4];
            const float sum_r  = hist1[0] + hist1[1] + hist1[2] + hist1[3] + hist1[4];
            const float sum_ii = hist2[0] + hist2[1] + hist2[2] + hist2[3] + hist2[4];
            const float sum_rr = hist3[0] + hist3[1] + hist3[2] + hist3[3] + hist3[4];
            const float sum_ir = hist4[0] + hist4[1] + hist4[2] + hist4[3] + hist4[4];

            // faithful to reference: reference mean uses sum_i
            const float mi = sum_i * inv_npix;
            const float mr = mi;

            const float var_r = sum_rr - 2.0f * mr * sum_r + npix * mr * mr;
            const float var_i = sum_ii - 2.0f * mi * sum_i + npix * mi * mi;
            const float cross = sum_ir - mr * sum_i - mi * sum_r + npix * mi * mr;

            const float ci = ch_i[2];
            const float cr = ch_r[2];

            // gradients: central inside, one-sided at edges (spacing 1)
            float gxi, gxr, gyi, gyr, gzi, gzr;
            if (gx == 0) {
                gxi = st_i[sz][ty + 2][tx + 3] - ci;
                gxr = st_r[sz][ty + 2][tx + 3] - cr;
            } else if (gx == N - 1) {
                gxi = ci - st_i[sz][ty + 2][tx + 1];
                gxr = cr - st_r[sz][ty + 2][tx + 1];
            } else {
                gxi = 0.5f * (st_i[sz][ty + 2][tx + 3] - st_i[sz][ty + 2][tx + 1]);
                gxr = 0.5f * (st_r[sz][ty + 2][tx + 3] - st_r[sz][ty + 2][tx + 1]);
            }
            if (gy == 0) {
                gyi = st_i[sz][ty + 3][tx + 2] - ci;
                gyr = st_r[sz][ty + 3][tx + 2] - cr;
            } else if (gy == N - 1) {
                gyi = ci - st_i[sz][ty + 1][tx + 2];
                gyr = cr - st_r[sz][ty + 1][tx + 2];
            } else {
                gyi = 0.5f * (st_i[sz][ty + 3][tx + 2] - st_i[sz][ty + 1][tx + 2]);
                gyr = 0.5f * (st_r[sz][ty + 3][tx + 2] - st_r[sz][ty + 1][tx + 2]);
            }
            if (z == 0) {
                gzi = ch_i[3] - ci;
                gzr = ch_r[3] - cr;
            } else if (z == N - 1) {
                gzi = ci - ch_i[1];
                gzr = cr - ch_r[1];
            } else {
                gzi = 0.5f * (ch_i[3] - ch_i[1]);
                gzr = 0.5f * (ch_r[3] - ch_r[1]);
            }

            const float gd = 0.5f * (gzi + gzr);   // axis D (z)
            const float gh = 0.5f * (gyi + gyr);   // axis H (y)
            const float gw = 0.5f * (gxi + gxr);   // axis W (x)

            const float factor =
                2.0f * cross / (var_i * var_r + 1e-6f) * (ci - cross / var_r * cr);

            const size_t idx = (size_t)z * NP + (size_t)gy * N + gx;
            out[idx]          = -factor * gd;
            out[NV + idx]     = -factor * gh;
            out[2 * NV + idx] = -factor * gw;
        }
    }
}

// ---------------------------------------------------------------------------
extern "C" void kernel_launch(void* const* d_in, const int* in_sizes, int n_in,
                              void* d_out, int out_size)
{
    const float* img = (const float*)d_in[0];   // image
    // d_in[1] = mask (unused, faithful to reference)
    const float* ref = (const float*)d_in[2];   // reference_image
    // d_in[3] = reference_mask (unused)
    float* out = (float*)d_out;

    dim3 block(32, TY, 1);
    dim3 grid(N / TX, N / TY, 1);
    ncc_fused_kernel<<<grid, block>>>(img, ref, out);
}

// round 3
// speedup vs baseline: 1.8630x; 1.8630x over previous
#include <cuda_runtime.h>
#include <cstdint>

#define N 256
#define NP 65536u
#define NVOX 16777216u

__device__ float g_sum[5][16777216];

// ===========================================================================
// Kernel 1: 5x5 box in X and Y of the 5 moment quantities, per z-plane.
// z-chunked (16 planes per CTA) with software-pipelined halo prefetch.
// ===========================================================================
#define K1_TX 32
#define K1_TY 32
#define K1_HX 36
#define K1_HY 36
#define K1_ZC 16
#define K1_HALO_N (K1_HX * K1_HY)   // 1296

__global__ __launch_bounds__(1024, 1) void boxxy_kernel(
    const float* __restrict__ img, const float* __restrict__ ref)
{
    __shared__ float si[K1_HY][K1_HX + 1];
    __shared__ float sr[K1_HY][K1_HX + 1];
    __shared__ float hs[5][K1_HY][K1_TX + 1];

    const int tx = threadIdx.x, ty = threadIdx.y;
    const int tid = ty * 32 + tx;
    const int x0 = blockIdx.x * K1_TX;
    const int y0 = blockIdx.y * K1_TY;
    const int z0 = blockIdx.z * K1_ZC;

    // Per-thread halo positions (2 max: tid, tid+1024)
    const int p0 = tid;
    const int p1 = tid + 1024;
    const int ly0 = p0 / K1_HX, lx0 = p0 - ly0 * K1_HX;
    const int ly1 = p1 / K1_HX, lx1 = p1 - ly1 * K1_HX;
    const int gx0a = x0 - 2 + lx0, gy0a = y0 - 2 + ly0;
    const int gx1a = x0 - 2 + lx1, gy1a = y0 - 2 + ly1;
    const bool in0 = (gx0a >= 0) & (gx0a < N) & (gy0a >= 0) & (gy0a < N);
    const bool in1 = (p1 < K1_HALO_N) & (gx1a >= 0) & (gx1a < N) & (gy1a >= 0) & (gy1a < N);
    const unsigned off0 = (unsigned)gy0a * N + (unsigned)gx0a;
    const unsigned off1 = (unsigned)gy1a * N + (unsigned)gx1a;

    // hsum positions
    const int hp0 = tid;
    const int hp1 = tid + 1024;
    const int hly0 = hp0 >> 5, hlx0 = hp0 & 31;
    const int hly1 = hp1 >> 5, hlx1 = hp1 & 31;
    const bool hact1 = hp1 < K1_HY * K1_TX;  // 1152

    // prefetch plane z0
    unsigned zoff = (unsigned)z0 * NP;
    float pi0 = in0 ? __ldg(img + zoff + off0) : 0.0f;
    float pr0 = in0 ? __ldg(ref + zoff + off0) : 0.0f;
    float pi1 = in1 ? __ldg(img + zoff + off1) : 0.0f;
    float pr1 = in1 ? __ldg(ref + zoff + off1) : 0.0f;

    for (int zi = 0; zi < K1_ZC; ++zi) {
        const int z = z0 + zi;

        // commit prefetched plane to shared
        si[ly0][lx0] = pi0;
        sr[ly0][lx0] = pr0;
        if (p1 < K1_HALO_N) { si[ly1][lx1] = pi1; sr[ly1][lx1] = pr1; }
        __syncthreads();

        // issue prefetch for next plane (overlaps with compute below)
        if (zi + 1 < K1_ZC) {
            unsigned zo = (unsigned)(z + 1) * NP;
            pi0 = in0 ? __ldg(img + zo + off0) : 0.0f;
            pr0 = in0 ? __ldg(ref + zo + off0) : 0.0f;
            pi1 = in1 ? __ldg(img + zo + off1) : 0.0f;
            pr1 = in1 ? __ldg(ref + zo + off1) : 0.0f;
        }

        // horizontal 5-tap sums of 5 quantities
        {
            float a0 = 0.f, a1 = 0.f, a2 = 0.f, a3 = 0.f, a4 = 0.f;
#pragma unroll
            for (int d = 0; d < 5; d++) {
                float vi = si[hly0][hlx0 + d];
                float vr = sr[hly0][hlx0 + d];
                a0 += vi; a1 += vr; a2 += vi * vi; a3 += vr * vr; a4 += vi * vr;
            }
            hs[0][hly0][hlx0] = a0; hs[1][hly0][hlx0] = a1; hs[2][hly0][hlx0] = a2;
            hs[3][hly0][hlx0] = a3; hs[4][hly0][hlx0] = a4;
            if (hact1) {
                float b0 = 0.f, b1 = 0.f, b2 = 0.f, b3 = 0.f, b4 = 0.f;
#pragma unroll
                for (int d = 0; d < 5; d++) {
                    float vi = si[hly1][hlx1 + d];
                    float vr = sr[hly1][hlx1 + d];
                    b0 += vi; b1 += vr; b2 += vi * vi; b3 += vr * vr; b4 += vi * vr;
                }
                hs[0][hly1][hlx1] = b0; hs[1][hly1][hlx1] = b1; hs[2][hly1][hlx1] = b2;
                hs[3][hly1][hlx1] = b3; hs[4][hly1][hlx1] = b4;
            }
        }
        __syncthreads();

        // vertical 5-tap + store intermediates
        const unsigned out_off = (unsigned)z * NP + (unsigned)(y0 + ty) * N + (unsigned)(x0 + tx);
#pragma unroll
        for (int q = 0; q < 5; q++) {
            float s = 0.f;
#pragma unroll
            for (int d = 0; d < 5; d++) s += hs[q][ty + d][tx];
            g_sum[q][out_off] = s;
        }
        __syncthreads();   // protect si/sr + hs before next iteration overwrites
    }
}

// ===========================================================================
// Kernel 2: sliding 5-deep z register ring over the intermediates + gradients
// + force epilogue. Thread per (x,y), marching a 32-plane z chunk.
// ===========================================================================
#define K2_ZC 32

__global__ __launch_bounds__(256) void zbox_final_kernel(
    const float* __restrict__ img, const float* __restrict__ ref,
    float* __restrict__ out)
{
    const int x = threadIdx.x;
    const int y = blockIdx.x;
    const int z0 = blockIdx.y * K2_ZC;
    const unsigned base = (unsigned)y * N + (unsigned)x;

    const float npix = 125.0f;
    const float inv_npix = 1.0f / 125.0f;

    // ring[q][k]: after push in iter z, ring[q][0..4] = planes z-2..z+2
    float ring[5][5];
    float c_i[3], c_r[3];   // centers: after push, planes z-1, z, z+1

    // prologue: ring[.][1..4] = planes z0-2 .. z0+1
#pragma unroll
    for (int k = 0; k < 4; k++) {
        int zz = z0 - 2 + k;
        bool in = (zz >= 0) & (zz < N);
        unsigned o = (unsigned)(in ? zz : 0) * NP + base;
#pragma unroll
        for (int q = 0; q < 5; q++)
            ring[q][k + 1] = in ? __ldg(&g_sum[q][o]) : 0.0f;
    }
    // centers: c[1] = z0-1, c[2] = z0
    {
        bool inm = (z0 - 1) >= 0;
        unsigned om = (unsigned)(inm ? (z0 - 1) : 0) * NP + base;
        c_i[1] = inm ? __ldg(img + om) : 0.0f;
        c_r[1] = inm ? __ldg(ref + om) : 0.0f;
        unsigned oc = (unsigned)z0 * NP + base;
        c_i[2] = __ldg(img + oc);
        c_r[2] = __ldg(ref + oc);
    }

    for (int z = z0; z < z0 + K2_ZC; ++z) {
        // shift rings
#pragma unroll
        for (int q = 0; q < 5; q++) {
#pragma unroll
            for (int k = 0; k < 4; k++) ring[q][k] = ring[q][k + 1];
        }
        c_i[0] = c_i[1]; c_i[1] = c_i[2];
        c_r[0] = c_r[1]; c_r[1] = c_r[2];

        // push plane z+2 (g_sum) and z+1 (centers)
        {
            int zz = z + 2;
            bool in = zz < N;
            unsigned o = (unsigned)(in ? zz : 0) * NP + base;
#pragma unroll
            for (int q = 0; q < 5; q++)
                ring[q][4] = in ? __ldg(&g_sum[q][o]) : 0.0f;
            int zc = z + 1;
            bool inc = zc < N;
            unsigned oc = (unsigned)(inc ? zc : 0) * NP + base;
            c_i[2] = inc ? __ldg(img + oc) : 0.0f;
            c_r[2] = inc ? __ldg(ref + oc) : 0.0f;
        }

        // neighbor loads at plane z (x±1, y±1), edge-adjusted
        const unsigned idx = (unsigned)z * NP + base;
        const float ci = c_i[1], cr = c_r[1];

        float xi_p = (x < N - 1) ? __ldg(img + idx + 1) : 0.f;
        float xi_m = (x > 0)     ? __ldg(img + idx - 1) : 0.f;
        float xr_p = (x < N - 1) ? __ldg(ref + idx + 1) : 0.f;
        float xr_m = (x > 0)     ? __ldg(ref + idx - 1) : 0.f;
        float yi_p = (y < N - 1) ? __ldg(img + idx + N) : 0.f;
        float yi_m = (y > 0)     ? __ldg(img + idx - N) : 0.f;
        float yr_p = (y < N - 1) ? __ldg(ref + idx + N) : 0.f;
        float yr_m = (y > 0)     ? __ldg(ref + idx - N) : 0.f;

        // z-box sums
        float sum_i  = ring[0][0] + ring[0][1] + ring[0][2] + ring[0][3] + ring[0][4];
        float sum_r  = ring[1][0] + ring[1][1] + ring[1][2] + ring[1][3] + ring[1][4];
        float sum_ii = ring[2][0] + ring[2][1] + ring[2][2] + ring[2][3] + ring[2][4];
        float sum_rr = ring[3][0] + ring[3][1] + ring[3][2] + ring[3][3] + ring[3][4];
        float sum_ir = ring[4][0] + ring[4][1] + ring[4][2] + ring[4][3] + ring[4][4];

        // faithful to reference: reference mean uses sum_i
        const float mi = sum_i * inv_npix;
        const float mr = mi;

        const float var_r = sum_rr - 2.0f * mr * sum_r + npix * mr * mr;
        const float var_i = sum_ii - 2.0f * mi * sum_i + npix * mi * mi;
        const float cross = sum_ir - mr * sum_i - mi * sum_r + npix * mi * mr;

        // gradients: central inside, one-sided at edges
        float gxi, gxr, gyi, gyr, gzi, gzr;
        if (x == 0)          { gxi = xi_p - ci; gxr = xr_p - cr; }
        else if (x == N - 1) { gxi = ci - xi_m; gxr = cr - xr_m; }
        else { gxi = 0.5f * (xi_p - xi_m); gxr = 0.5f * (xr_p - xr_m); }

        if (y == 0)          { gyi = yi_p - ci; gyr = yr_p - cr; }
        else if (y == N - 1) { gyi = ci - yi_m; gyr = cr - yr_m; }
        else { gyi = 0.5f * (yi_p - yi_m); gyr = 0.5f * (yr_p - yr_m); }

        if (z == 0)          { gzi = c_i[2] - ci; gzr = c_r[2] - cr; }
        else if (z == N - 1) { gzi = ci - c_i[0]; gzr = cr - c_r[0]; }
        else { gzi = 0.5f * (c_i[2] - c_i[0]); gzr = 0.5f * (c_r[2] - c_r[0]); }

        const float gd = 0.5f * (gzi + gzr);
        const float gh = 0.5f * (gyi + gyr);
        const float gw = 0.5f * (gxi + gxr);

        const float factor =
            2.0f * cross / (var_i * var_r + 1e-6f) * (ci - cross / var_r * cr);

        out[idx]             = -factor * gd;
        out[NVOX + idx]      = -factor * gh;
        out[2u * NVOX + idx] = -factor * gw;
    }
}

// ---------------------------------------------------------------------------
extern "C" void kernel_launch(void* const* d_in, const int* in_sizes, int n_in,
                              void* d_out, int out_size)
{
    const float* img = (const float*)d_in[0];   // image
    const float* ref = (const float*)d_in[2];   // reference_image
    float* out = (float*)d_out;

    {
        dim3 block(32, 32, 1);
        dim3 grid(N / K1_TX, N / K1_TY, N / K1_ZC);
        boxxy_kernel<<<grid, block>>>(img, ref);
    }
    {
        dim3 block(256, 1, 1);
        dim3 grid(N, N / K2_ZC, 1);
        zbox_final_kernel<<<grid, block>>>(img, ref, out);
    }
}